// round 3
// baseline (speedup 1.0000x reference)
#include <cuda_runtime.h>
#include <cstdint>

// ---------------- problem constants ----------------
#define NTOT   61440          // total nodes
#define NODES  30
#define BATCH  2048           // NTOT / NODES
#define INCH   12
#define EDGES  491520
#define C0     128
#define C1     512
#define C2     128
#define FCIN   (C2*NODES)     // 3840
#define FCOUT  72

// ---------------- scratch (device globals; no runtime alloc allowed) ----------------
__device__ float g_h   [NTOT*INCH];
__device__ float g_deg [NTOT];
__device__ float g_dinv[NTOT];
__device__ float g_X0  [BATCH*INCH*NODES];
__device__ float g_X1  [(size_t)BATCH*C0*NODES];
__device__ float g_X2  [(size_t)BATCH*C1*NODES];
__device__ float g_X3  [(size_t)BATCH*C2*NODES];

// ---------------- GCN: h = x @ W^T ; deg init ----------------
__global__ void k_gcn_lin(const float* __restrict__ x, const float* __restrict__ w) {
    __shared__ float sw[INCH*INCH];
    if (threadIdx.x < INCH*INCH) sw[threadIdx.x] = w[threadIdx.x];
    __syncthreads();
    int n = blockIdx.x*blockDim.x + threadIdx.x;
    if (n >= NTOT) return;
    g_deg[n] = 1.0f;   // self-loop
    float xr[INCH];
#pragma unroll
    for (int i = 0; i < INCH; i++) xr[i] = x[n*INCH + i];
#pragma unroll
    for (int c = 0; c < INCH; c++) {
        float s = 0.f;
#pragma unroll
        for (int i = 0; i < INCH; i++) s = fmaf(sw[c*INCH + i], xr[i], s);
        g_h[n*INCH + c] = s;
    }
}

__global__ void k_deg_count(const int* __restrict__ dst) {
    int e = blockIdx.x*blockDim.x + threadIdx.x;
    if (e < EDGES) atomicAdd(&g_deg[dst[e]], 1.0f);
}

// dinv + init X0 (self-loop term + bias), layout X0[b][c][t]
__global__ void k_dinv_init(const float* __restrict__ gcn_b) {
    int n = blockIdx.x*blockDim.x + threadIdx.x;
    if (n >= NTOT) return;
    float di = rsqrtf(g_deg[n]);
    g_dinv[n] = di;
    float s = di*di;
    int b = n / NODES, t = n % NODES;
#pragma unroll
    for (int c = 0; c < INCH; c++)
        g_X0[((size_t)b*INCH + c)*NODES + t] = fmaf(s, g_h[n*INCH + c], gcn_b[c]);
}

__global__ void k_scatter(const int* __restrict__ src,
                          const int* __restrict__ dst) {
    int id = blockIdx.x*blockDim.x + threadIdx.x;
    if (id >= EDGES*INCH) return;
    int e = id / INCH, c = id % INCH;
    int s = src[e], d = dst[e];
    float v = g_dinv[s]*g_dinv[d]*g_h[s*INCH + c];
    int b = d / NODES, t = d % NODES;
    atomicAdd(&g_X0[((size_t)b*INCH + c)*NODES + t], v);
}

// ---------------- TCN block: X = relu(relu(causal_conv(X)+cb) + (1x1(X)+db)) ----------------
// Scatter-form causal dilated conv: x[t'] contributes w2->acc[t'], w1->acc[t'+D], w0->acc[t'+2D].
template<int IN, int OUT, int DIL, int NT, bool USE_SMEM>
__device__ __forceinline__ void tcn_body(
      const float* __restrict__ Xin, float* __restrict__ Xout,
      const float* __restrict__ cw, const float* __restrict__ cb,
      const float* __restrict__ dw, const float* __restrict__ db) {
    extern __shared__ float sx[];
    int b = blockIdx.x;
    const float* xb = Xin + (size_t)b*IN*NODES;
    if (USE_SMEM) {
        for (int i = threadIdx.x; i < IN*NODES; i += NT) sx[i] = xb[i];
        __syncthreads();
    }
    const float* xbase = USE_SMEM ? sx : xb;

    for (int oc = threadIdx.x; oc < OUT; oc += NT) {
        float acc[NODES], dac[NODES];
        float cbv = cb[oc], dbv = db[oc];
#pragma unroll
        for (int t = 0; t < NODES; t++) { acc[t] = cbv; dac[t] = dbv; }
        const float* wrow = cw + (size_t)oc*IN*3;
        const float* drow = dw + (size_t)oc*IN;
        for (int ic = 0; ic < IN; ic++) {
            float w0 = wrow[ic*3+0], w1 = wrow[ic*3+1], w2 = wrow[ic*3+2];
            float dv = drow[ic];
            const float* xr = xbase + ic*NODES;
#pragma unroll
            for (int t = 0; t < NODES; t++) {
                float xv = xr[t];
                acc[t] = fmaf(w2, xv, acc[t]);
                dac[t] = fmaf(dv, xv, dac[t]);
                if (t + DIL   < NODES) acc[t+DIL]   = fmaf(w1, xv, acc[t+DIL]);
                if (t + 2*DIL < NODES) acc[t+2*DIL] = fmaf(w0, xv, acc[t+2*DIL]);
            }
        }
        float* ob = Xout + ((size_t)b*OUT + oc)*NODES;
#pragma unroll
        for (int t = 0; t < NODES; t++) {
            float o = fmaxf(acc[t], 0.f) + dac[t];
            ob[t] = fmaxf(o, 0.f);
        }
    }
}

__global__ void __launch_bounds__(128)
k_tcn0(const float* __restrict__ cw, const float* __restrict__ cb,
       const float* __restrict__ dw, const float* __restrict__ db) {
    tcn_body<INCH, C0, 1, 128, true>(g_X0, g_X1, cw, cb, dw, db);
}
__global__ void __launch_bounds__(256)
k_tcn1(const float* __restrict__ cw, const float* __restrict__ cb,
       const float* __restrict__ dw, const float* __restrict__ db) {
    tcn_body<C0, C1, 3, 256, true>(g_X1, g_X2, cw, cb, dw, db);
}
__global__ void __launch_bounds__(128)
k_tcn2(const float* __restrict__ cw, const float* __restrict__ cb,
       const float* __restrict__ dw, const float* __restrict__ db) {
    tcn_body<C1, C2, 9, 128, false>(g_X2, g_X3, cw, cb, dw, db);
}

// ---------------- FC: out[2048,72] = T[2048,3840] @ W^T + b ----------------
#define FC_BM 32
#define FC_BK 32
__global__ void __launch_bounds__(256)
k_fc(const float* __restrict__ W, const float* __restrict__ bias,
     float* __restrict__ out) {
    const float* T = g_X3;
    __shared__ float Ts[FC_BK][FC_BM+1];   // [k][m]
    __shared__ float Ws[80][FC_BK+1];      // [n][k], n padded 72->80
    int b0 = blockIdx.x * FC_BM;
    int tid = threadIdx.x;
    int tr = tid / 16;    // 0..15 -> rows tr*2 + {0,1}
    int tc = tid % 16;    // 0..15 -> cols tc*5 + {0..4}
    float acc[2][5] = {};
    for (int k0 = 0; k0 < FCIN; k0 += FC_BK) {
        for (int i = tid; i < FC_BM*FC_BK; i += 256) {
            int m = i / FC_BK, k = i % FC_BK;
            Ts[k][m] = T[(size_t)(b0+m)*FCIN + k0 + k];
        }
        for (int i = tid; i < 80*FC_BK; i += 256) {
            int n = i / FC_BK, k = i % FC_BK;
            Ws[n][k] = (n < FCOUT) ? W[(size_t)n*FCIN + k0 + k] : 0.f;
        }
        __syncthreads();
#pragma unroll
        for (int kk = 0; kk < FC_BK; kk++) {
            float a0 = Ts[kk][tr*2+0];
            float a1 = Ts[kk][tr*2+1];
#pragma unroll
            for (int j = 0; j < 5; j++) {
                float bv = Ws[tc*5+j][kk];
                acc[0][j] = fmaf(a0, bv, acc[0][j]);
                acc[1][j] = fmaf(a1, bv, acc[1][j]);
            }
        }
        __syncthreads();
    }
#pragma unroll
    for (int i = 0; i < 2; i++) {
        int b = b0 + tr*2 + i;
#pragma unroll
        for (int j = 0; j < 5; j++) {
            int o = tc*5 + j;
            if (o < FCOUT) out[(size_t)b*FCOUT + o] = acc[i][j] + bias[o];
        }
    }
}

// ---------------- launch (kernel launches ONLY — graph-capturable) ----------------
extern "C" void kernel_launch(void* const* d_in, const int* in_sizes, int n_in,
                              void* d_out, int out_size) {
    const float* x     = (const float*)d_in[0];
    const int*   ei    = (const int*)d_in[1];   // [2, E] — JAX x64 disabled => int32
    const float* gcn_w = (const float*)d_in[2];
    const float* gcn_b = (const float*)d_in[3];
    const float* cw0   = (const float*)d_in[4];
    const float* cb0   = (const float*)d_in[5];
    const float* dw0   = (const float*)d_in[6];
    const float* db0   = (const float*)d_in[7];
    const float* cw1   = (const float*)d_in[8];
    const float* cb1   = (const float*)d_in[9];
    const float* dw1   = (const float*)d_in[10];
    const float* db1   = (const float*)d_in[11];
    const float* cw2   = (const float*)d_in[12];
    const float* cb2   = (const float*)d_in[13];
    const float* dw2   = (const float*)d_in[14];
    const float* db2   = (const float*)d_in[15];
    const float* fc_w  = (const float*)d_in[16];
    const float* fc_b  = (const float*)d_in[17];
    float* out = (float*)d_out;

    const int* src = ei;
    const int* dst = ei + EDGES;

    // GCN
    k_gcn_lin<<<(NTOT+255)/256, 256>>>(x, gcn_w);
    k_deg_count<<<(EDGES+255)/256, 256>>>(dst);
    k_dinv_init<<<(NTOT+255)/256, 256>>>(gcn_b);
    k_scatter<<<(EDGES*INCH+255)/256, 256>>>(src, dst);

    // TCN blocks
    k_tcn0<<<BATCH, 128, INCH*NODES*4>>>(cw0, cb0, dw0, db0);
    k_tcn1<<<BATCH, 256, C0*NODES*4 >>>(cw1, cb1, dw1, db1);
    k_tcn2<<<BATCH, 128, 0          >>>(cw2, cb2, dw2, db2);

    // FC
    k_fc<<<BATCH/FC_BM, 256>>>(fc_w, fc_b, out);
}

// round 5
// speedup vs baseline: 1.4572x; 1.4572x over previous
#include <cuda_runtime.h>
#include <cstdint>

// ---------------- problem constants ----------------
#define NTOT   61440
#define NODES  30
#define BATCH  2048
#define INCH   12
#define EDGES  491520
#define C0     128
#define C1     512
#define C2     128
#define FCIN   (C2*NODES)     // 3840
#define FCOUT  72

// ---------------- scratch ----------------
__device__ float g_h   [NTOT*INCH];          // [n][c]
__device__ float g_deg [NTOT];
__device__ float g_dinv[NTOT];
__device__ float g_A0  [NTOT*INCH];          // [n][c] GCN output (node-major)
__device__ float g_X0  [(size_t)INCH*NODES*BATCH];   // [c][t][b]
__device__ float g_X1  [(size_t)C0*NODES*BATCH];
__device__ float g_X2  [(size_t)C1*NODES*BATCH];
__device__ float g_X3  [(size_t)C2*NODES*BATCH];

// ---------------- f32x2 helpers (ptxas won't auto-fuse; PTX-only) ----------------
__device__ __forceinline__ unsigned long long pack2(float lo, float hi) {
    unsigned long long r;
    asm("mov.b64 %0, {%1, %2};" : "=l"(r) : "f"(lo), "f"(hi));
    return r;
}
__device__ __forceinline__ unsigned long long dup2(float v) { return pack2(v, v); }
__device__ __forceinline__ void unpack2(unsigned long long v, float& lo, float& hi) {
    asm("mov.b64 {%0, %1}, %2;" : "=f"(lo), "=f"(hi) : "l"(v));
}
__device__ __forceinline__ void fma2(unsigned long long& d, unsigned long long a, unsigned long long b) {
    asm("fma.rn.f32x2 %0, %1, %2, %0;" : "+l"(d) : "l"(a), "l"(b));
}

// ---------------- GCN ----------------
__global__ void k_gcn_lin(const float* __restrict__ x, const float* __restrict__ w) {
    __shared__ float sw[INCH*INCH];
    if (threadIdx.x < INCH*INCH) sw[threadIdx.x] = w[threadIdx.x];
    __syncthreads();
    int n = blockIdx.x*blockDim.x + threadIdx.x;
    if (n >= NTOT) return;
    g_deg[n] = 1.0f;   // self-loop
    float xr[INCH];
#pragma unroll
    for (int i = 0; i < INCH; i++) xr[i] = x[n*INCH + i];
#pragma unroll
    for (int c = 0; c < INCH; c++) {
        float s = 0.f;
#pragma unroll
        for (int i = 0; i < INCH; i++) s = fmaf(sw[c*INCH + i], xr[i], s);
        g_h[n*INCH + c] = s;
    }
}

__global__ void k_deg_count(const int* __restrict__ dst) {
    int e = blockIdx.x*blockDim.x + threadIdx.x;
    if (e < EDGES) atomicAdd(&g_deg[dst[e]], 1.0f);
}

// dinv + A0 init with self-loop + bias (node-major, coalesced)
__global__ void k_dinv_init(const float* __restrict__ gcn_b) {
    int n = blockIdx.x*blockDim.x + threadIdx.x;
    if (n >= NTOT) return;
    float di = rsqrtf(g_deg[n]);
    g_dinv[n] = di;
    float s = di*di;
#pragma unroll
    for (int c = 0; c < INCH; c++)
        g_A0[n*INCH + c] = fmaf(s, g_h[n*INCH + c], gcn_b[c]);
}

__global__ void k_scatter(const int* __restrict__ src, const int* __restrict__ dst) {
    int id = blockIdx.x*blockDim.x + threadIdx.x;
    if (id >= EDGES*INCH) return;
    int e = id / INCH, c = id % INCH;
    int s = src[e], d = dst[e];
    float v = g_dinv[s]*g_dinv[d]*g_h[s*INCH + c];
    atomicAdd(&g_A0[d*INCH + c], v);
}

// transpose [n=(b,t)][c] -> [c][t][b]  (32 batches per block, smem tile)
__global__ void __launch_bounds__(256) k_transpose() {
    __shared__ float s[32*NODES*INCH];   // 11520 floats = 45KB
    int b0 = blockIdx.x * 32;
    for (int i = threadIdx.x; i < 32*NODES*INCH; i += 256)
        s[i] = g_A0[(size_t)b0*NODES*INCH + i];
    __syncthreads();
    for (int i = threadIdx.x; i < INCH*NODES*32; i += 256) {
        int c = i / (NODES*32);
        int r = i % (NODES*32);
        int t = r / 32, bl = r % 32;
        g_X0[((size_t)c*NODES + t)*BATCH + b0 + bl] = s[(bl*NODES + t)*INCH + c];
    }
}

// ---------------- TCN as GEMM tile (batch-last), f32x2 ----------------
// out[oc][t][b] : acc1 = causal conv (taps k=0,1,2 at t-2D,t-D,t), acc2 = 1x1 down (at t)
// X = relu( relu(acc1+cb) + acc2+db )
template<int IN, int OUT, int DIL, int BK>
__device__ __forceinline__ void tcn_gemm_body(
      const float* __restrict__ Xin, float* __restrict__ Xout,
      const float* __restrict__ cw, const float* __restrict__ cb,
      const float* __restrict__ dw, const float* __restrict__ db) {
    constexpr int BN = 64, BM = 128;
    __shared__ float A_s[BK*3*BN];       // [ic][k][b]
    __shared__ float B_s[BM*BK*4];       // [oc][ic][w0,w1,w2,down]
    const int t   = blockIdx.x;
    const int b0  = blockIdx.y * BN;
    const int oc0 = blockIdx.z * BM;
    const int tid = threadIdx.x;
    const int tx = tid & 15, ty = tid >> 4;
    const int bb = tx*4, oct = ty*8;

    unsigned long long acc1[8][2], acc2[8][2];
#pragma unroll
    for (int j = 0; j < 8; j++) { acc1[j][0]=acc1[j][1]=acc2[j][0]=acc2[j][1]=0ULL; }

    for (int ic0 = 0; ic0 < IN; ic0 += BK) {
        // stage A (coalesced along b)
#pragma unroll
        for (int i = tid; i < BK*3*BN; i += 256) {
            int ic = i/(3*BN); int r = i%(3*BN); int kk = r/BN; int b = r%BN;
            int tk = t + (kk-2)*DIL;
            A_s[i] = (tk >= 0) ? Xin[((size_t)(ic0+ic)*NODES + tk)*BATCH + b0 + b] : 0.f;
        }
        // stage B: 3 conv taps + downsample per (oc, ic)
#pragma unroll
        for (int i = tid; i < BM*BK*4; i += 256) {
            int oc = i/(BK*4); int r = i%(BK*4); int ic = r/4; int w = r&3;
            float v;
            if (w < 3) v = cw[((size_t)(oc0+oc)*IN + ic0+ic)*3 + w];
            else       v = dw[(size_t)(oc0+oc)*IN + ic0+ic];
            B_s[i] = v;
        }
        __syncthreads();
#pragma unroll
        for (int ic = 0; ic < BK; ic++) {
            unsigned long long a2[3][2];
#pragma unroll
            for (int kk = 0; kk < 3; kk++) {
                const float4 v = *reinterpret_cast<const float4*>(&A_s[(ic*3+kk)*BN + bb]);
                a2[kk][0] = pack2(v.x, v.y);
                a2[kk][1] = pack2(v.z, v.w);
            }
#pragma unroll
            for (int j = 0; j < 8; j++) {
                const float4 w = *reinterpret_cast<const float4*>(&B_s[((oct+j)*BK + ic)*4]);
                unsigned long long w0=dup2(w.x), w1=dup2(w.y), w2=dup2(w.z), w3=dup2(w.w);
                fma2(acc1[j][0], w0, a2[0][0]); fma2(acc1[j][1], w0, a2[0][1]);
                fma2(acc1[j][0], w1, a2[1][0]); fma2(acc1[j][1], w1, a2[1][1]);
                fma2(acc1[j][0], w2, a2[2][0]); fma2(acc1[j][1], w2, a2[2][1]);
                fma2(acc2[j][0], w3, a2[2][0]); fma2(acc2[j][1], w3, a2[2][1]);
            }
        }
        __syncthreads();
    }
    // epilogue
#pragma unroll
    for (int j = 0; j < 8; j++) {
        int oc = oc0 + oct + j;
        float cbv = cb[oc], dbv = db[oc];
        float c0,c1,c2,c3, d0,d1,d2,d3;
        unpack2(acc1[j][0], c0, c1); unpack2(acc1[j][1], c2, c3);
        unpack2(acc2[j][0], d0, d1); unpack2(acc2[j][1], d2, d3);
        float4 o;
        o.x = fmaxf(fmaxf(c0+cbv, 0.f) + d0 + dbv, 0.f);
        o.y = fmaxf(fmaxf(c1+cbv, 0.f) + d1 + dbv, 0.f);
        o.z = fmaxf(fmaxf(c2+cbv, 0.f) + d2 + dbv, 0.f);
        o.w = fmaxf(fmaxf(c3+cbv, 0.f) + d3 + dbv, 0.f);
        *reinterpret_cast<float4*>(&Xout[((size_t)oc*NODES + t)*BATCH + b0 + bb]) = o;
    }
}

__global__ void __launch_bounds__(256)
k_tcn0(const float* __restrict__ cw, const float* __restrict__ cb,
       const float* __restrict__ dw, const float* __restrict__ db) {
    tcn_gemm_body<INCH, C0, 1, 12>(g_X0, g_X1, cw, cb, dw, db);
}
__global__ void __launch_bounds__(256)
k_tcn1(const float* __restrict__ cw, const float* __restrict__ cb,
       const float* __restrict__ dw, const float* __restrict__ db) {
    tcn_gemm_body<C0, C1, 3, 8>(g_X1, g_X2, cw, cb, dw, db);
}
__global__ void __launch_bounds__(256)
k_tcn2(const float* __restrict__ cw, const float* __restrict__ cb,
       const float* __restrict__ dw, const float* __restrict__ db) {
    tcn_gemm_body<C1, C2, 9, 8>(g_X2, g_X3, cw, cb, dw, db);
}

// ---------------- FC: out[2048,72] = X3^T[b][k] @ W[o][k]^T + b ----------------
// X3 is [k=(c*30+t)][b] -> A-tile loads coalesced along b.
#define FC_BM 32
#define FC_BK 32
__global__ void __launch_bounds__(256)
k_fc(const float* __restrict__ W, const float* __restrict__ bias,
     float* __restrict__ out) {
    const float* T = g_X3;               // [k][b]
    __shared__ float Ts[FC_BK][FC_BM+1]; // [k][m]
    __shared__ float Ws[80][FC_BK+1];    // [n][k]
    int b0 = blockIdx.x * FC_BM;
    int tid = threadIdx.x;
    int tr = tid / 16;
    int tc = tid % 16;
    float acc[2][5] = {};
    for (int k0 = 0; k0 < FCIN; k0 += FC_BK) {
        for (int i = tid; i < FC_BK*FC_BM; i += 256) {
            int k = i / FC_BM, m = i % FC_BM;          // m fastest -> coalesced
            Ts[k][m] = T[(size_t)(k0+k)*BATCH + b0 + m];
        }
        for (int i = tid; i < 80*FC_BK; i += 256) {
            int n = i / FC_BK, k = i % FC_BK;
            Ws[n][k] = (n < FCOUT) ? W[(size_t)n*FCIN + k0 + k] : 0.f;
        }
        __syncthreads();
#pragma unroll
        for (int kk = 0; kk < FC_BK; kk++) {
            float a0 = Ts[kk][tr*2+0];
            float a1 = Ts[kk][tr*2+1];
#pragma unroll
            for (int j = 0; j < 5; j++) {
                float bv = Ws[tc*5+j][kk];
                acc[0][j] = fmaf(a0, bv, acc[0][j]);
                acc[1][j] = fmaf(a1, bv, acc[1][j]);
            }
        }
        __syncthreads();
    }
#pragma unroll
    for (int i = 0; i < 2; i++) {
        int b = b0 + tr*2 + i;
#pragma unroll
        for (int j = 0; j < 5; j++) {
            int o = tc*5 + j;
            if (o < FCOUT) out[(size_t)b*FCOUT + o] = acc[i][j] + bias[o];
        }
    }
}

// ---------------- launch (kernel launches ONLY) ----------------
extern "C" void kernel_launch(void* const* d_in, const int* in_sizes, int n_in,
                              void* d_out, int out_size) {
    const float* x     = (const float*)d_in[0];
    const int*   ei    = (const int*)d_in[1];
    const float* gcn_w = (const float*)d_in[2];
    const float* gcn_b = (const float*)d_in[3];
    const float* cw0   = (const float*)d_in[4];
    const float* cb0   = (const float*)d_in[5];
    const float* dw0   = (const float*)d_in[6];
    const float* db0   = (const float*)d_in[7];
    const float* cw1   = (const float*)d_in[8];
    const float* cb1   = (const float*)d_in[9];
    const float* dw1   = (const float*)d_in[10];
    const float* db1   = (const float*)d_in[11];
    const float* cw2   = (const float*)d_in[12];
    const float* cb2   = (const float*)d_in[13];
    const float* dw2   = (const float*)d_in[14];
    const float* db2   = (const float*)d_in[15];
    const float* fc_w  = (const float*)d_in[16];
    const float* fc_b  = (const float*)d_in[17];
    float* out = (float*)d_out;

    const int* src = ei;
    const int* dst = ei + EDGES;

    // GCN
    k_gcn_lin<<<(NTOT+255)/256, 256>>>(x, gcn_w);
    k_deg_count<<<(EDGES+255)/256, 256>>>(dst);
    k_dinv_init<<<(NTOT+255)/256, 256>>>(gcn_b);
    k_scatter<<<(EDGES*INCH+255)/256, 256>>>(src, dst);
    k_transpose<<<BATCH/32, 256>>>();

    // TCN blocks (GEMM tiles: grid = t x b-tiles x oc-tiles)
    k_tcn0<<<dim3(NODES, BATCH/64, C0/128), 256>>>(cw0, cb0, dw0, db0);
    k_tcn1<<<dim3(NODES, BATCH/64, C1/128), 256>>>(cw1, cb1, dw1, db1);
    k_tcn2<<<dim3(NODES, BATCH/64, C2/128), 256>>>(cw2, cb2, dw2, db2);

    // FC
    k_fc<<<BATCH/FC_BM, 256>>>(fc_w, fc_b, out);
}